// round 9
// baseline (speedup 1.0000x reference)
#include <cuda_runtime.h>
#include <cuda_bf16.h>
#include <math.h>

// PCL loss, single kernel, FENCE-FREE and ACQUIRE-FREE:
//   valid = target != -1
//   p     = (target==0) ? input[i*C + 0] : pc_input[cluster[i]]
//   loss  = sum(valid * (-weight * log(max(p, 1e-12)))) / max(sum(valid), 1)
//
// Ordering design: all cross-block communication goes through ATOMICS, which
// execute at the L2 coherence point (L1 bypassed). Per block:
//   atomicAdd(g_sum), atomicAdd(g_cnt)  -> partials merged at L2
//   atom.release.gpu.inc(g_done)        -> release publishes the adds; release
//                                          does NOT invalidate L1 (only acquire
//                                          does), so no CCTL.IVALL storm.
// The last block READS the totals via atomicAdd(x, 0) — coherent at L2, no
// acquire needed — writes out, and resets the accumulators (plain stores,
// made visible to the next graph replay by the kernel boundary). g_done
// self-resets via the inc wrap bound. One kernel node, no init kernel.
//
// Concurrency design: EPT=4 -> 2048 CTAs, ~32 regs, full occupancy (64
// warps/SM), 7 independent LDGs in flight per warp (3x128b + 4 gathers).

#define C_CLASSES 21
#define EPS 1e-12f
#define THREADS 256
#define EPT 4

__device__ float        g_sum = 0.0f;
__device__ unsigned int g_cnt = 0u;
__device__ unsigned int g_done = 0u;   // wraps to 0 via atom.inc bound

__global__ void __launch_bounds__(THREADS)
pcl_fused(const float* __restrict__ input,
          const float* __restrict__ weight,
          const float* __restrict__ pc,
          const int* __restrict__ target,
          const int* __restrict__ cluster,
          int n, float* __restrict__ out) {
    float lsum = 0.0f;
    unsigned int lcnt = 0u;

    const int i = (blockIdx.x * THREADS + threadIdx.x) * EPT;

    if (i + EPT <= n) {
        // 3 independent coalesced 128-bit loads
        int4   t4 = *reinterpret_cast<const int4*>(target + i);
        int4   c4 = *reinterpret_cast<const int4*>(cluster + i);
        float4 w4 = *reinterpret_cast<const float4*>(weight + i);

        int   t[EPT] = {t4.x, t4.y, t4.z, t4.w};
        int   c[EPT] = {c4.x, c4.y, c4.z, c4.w};
        float w[EPT] = {w4.x, w4.y, w4.z, w4.w};

        // branchless address select, then 4 independent gathers (MLP=4+3)
        const float* addr[EPT];
        #pragma unroll
        for (int k = 0; k < EPT; k++) {
            const float* a_bg = input + (long long)(i + k) * C_CLASSES;
            const float* a_fg = pc + c[k];
            addr[k] = (t[k] == 0) ? a_bg : a_fg;   // ISETP+SEL, no branch
        }
        float p[EPT];
        #pragma unroll
        for (int k = 0; k < EPT; k++) p[k] = __ldg(addr[k]);

        #pragma unroll
        for (int k = 0; k < EPT; k++) {
            bool valid = (t[k] != -1);
            float l = __logf(fmaxf(p[k], EPS));
            lsum += valid ? w[k] * l : 0.0f;
            lcnt += valid ? 1u : 0u;
        }
    } else {
        for (int k = i; k < n; k++) {
            int tk = target[k];
            if (tk != -1) {
                float pk = (tk == 0) ? __ldg(input + (long long)k * C_CLASSES)
                                     : __ldg(pc + cluster[k]);
                lsum += weight[k] * __logf(fmaxf(pk, EPS));
                lcnt++;
            }
        }
    }

    // warp reduction
    #pragma unroll
    for (int off = 16; off > 0; off >>= 1) {
        lsum += __shfl_xor_sync(0xFFFFFFFFu, lsum, off);
        lcnt += __shfl_xor_sync(0xFFFFFFFFu, lcnt, off);
    }

    // block reduction (8 warps)
    __shared__ float        s_sum[8];
    __shared__ unsigned int s_cnt[8];
    __shared__ int          s_is_last;
    int wid = threadIdx.x >> 5;
    int lid = threadIdx.x & 31;
    if (lid == 0) { s_sum[wid] = lsum; s_cnt[wid] = lcnt; }
    __syncthreads();
    if (threadIdx.x == 0) {
        float        bs = 0.0f;
        unsigned int bc = 0u;
        #pragma unroll
        for (int w8 = 0; w8 < 8; w8++) { bs += s_sum[w8]; bc += s_cnt[w8]; }
        // merge partials at the L2 coherence point (atomics bypass L1)
        atomicAdd(&g_sum, bs);
        atomicAdd(&g_cnt, bc);
        // release-only inc: publishes this thread's atomics/stores before the
        // counter bump; wraps to 0 at gridDim.x-1 (self-reset, replay-safe).
        unsigned int prev;
        asm volatile("atom.release.gpu.global.inc.u32 %0, [%1], %2;"
                     : "=r"(prev)
                     : "l"(&g_done), "r"(gridDim.x - 1)
                     : "memory");
        s_is_last = (prev == gridDim.x - 1) ? 1 : 0;
    }
    __syncthreads();

    if (s_is_last && threadIdx.x == 0) {
        // coherent reads at L2 — no acquire, no L1 invalidate needed
        float        ts = atomicAdd(&g_sum, 0.0f);
        unsigned int tc = atomicAdd(&g_cnt, 0u);
        float nv = fmaxf((float)tc, 1.0f);
        *out = -ts / nv;
        // reset accumulators for the next graph replay; visibility is
        // guaranteed by the kernel boundary before the next launch.
        g_sum = 0.0f;
        g_cnt = 0u;
    }
}

extern "C" void kernel_launch(void* const* d_in, const int* in_sizes, int n_in,
                              void* d_out, int out_size) {
    const float* input   = (const float*)d_in[0];   // [N, 21]
    const float* weight  = (const float*)d_in[1];   // [N]
    const float* pc      = (const float*)d_in[2];   // [4096]
    const int*   target  = (const int*)d_in[3];     // [N] int32
    const int*   cluster = (const int*)d_in[4];     // [N] int32
    float* out = (float*)d_out;

    int n = in_sizes[1];   // weight element count == N

    int per_block = THREADS * EPT;                 // 1024
    int blocks = (n + per_block - 1) / per_block;  // 2048 for N=2M
    if (blocks < 1) blocks = 1;
    pcl_fused<<<blocks, THREADS>>>(input, weight, pc, target, cluster, n, out);
}